// round 6
// baseline (speedup 1.0000x reference)
#include <cuda_runtime.h>
#include <cstdint>

#define N_OBJ   8192
#define N_FLOOR 8192
#define STEPS   100

#define DT_F        0.01f
#define TWO_R       0.002f
#define SLEEP_TH_F  0.098f        // DT * 9.8
#define EPS_F       1e-12f

#define GY   8
#define TILE (N_FLOOR / GY)       // 1024 floor points per y-block

// partial per-object min horizontal squared distance, one row per floor chunk
__device__ float g_part[GY][N_OBJ];

// ---------------------------------------------------------------------------
// packed f32x2 helpers (sm_10x 2xFP32 datapath; only reachable via PTX)
// ---------------------------------------------------------------------------
__device__ __forceinline__ unsigned long long pack2(float lo, float hi) {
    unsigned long long r;
    asm("mov.b64 %0, {%1, %2};" : "=l"(r) : "f"(lo), "f"(hi));
    return r;
}
__device__ __forceinline__ void unpack2(float& lo, float& hi, unsigned long long v) {
    asm("mov.b64 {%0, %1}, %2;" : "=f"(lo), "=f"(hi) : "l"(v));
}
__device__ __forceinline__ unsigned long long add2(unsigned long long a, unsigned long long b) {
    unsigned long long r;
    asm("add.rn.f32x2 %0, %1, %2;" : "=l"(r) : "l"(a), "l"(b));
    return r;
}
__device__ __forceinline__ unsigned long long mul2(unsigned long long a, unsigned long long b) {
    unsigned long long r;
    asm("mul.rn.f32x2 %0, %1, %2;" : "=l"(r) : "l"(a), "l"(b));
    return r;
}
__device__ __forceinline__ unsigned long long fma2(unsigned long long a, unsigned long long b,
                                                   unsigned long long c) {
    unsigned long long r;
    asm("fma.rn.f32x2 %0, %1, %2, %3;" : "=l"(r) : "l"(a), "l"(b), "l"(c));
    return r;
}

// ---------------------------------------------------------------------------
// Kernel A: partial minxy2 over one floor chunk.
// grid = (N_OBJ/256, GY), block = 256 threads (1 object each).
// Two floor points per iteration via packed f32x2 (FFMA2 path).
// ---------------------------------------------------------------------------
__global__ void __launch_bounds__(256) minxy_kernel(
    const float* __restrict__ obj, const float* __restrict__ flr)
{
    // sf[j].x = pack(-fx[2j], -fx[2j+1]), sf[j].y = pack(-fy[2j], -fy[2j+1])
    __shared__ ulonglong2 sf[TILE / 2];

    const int objIdx = blockIdx.x * 256 + threadIdx.x;
    const float ox = obj[objIdx * 3 + 0];
    const float oy = obj[objIdx * 3 + 1];
    const unsigned long long ox2 = pack2(ox, ox);
    const unsigned long long oy2 = pack2(oy, oy);

    const int fbase = blockIdx.y * TILE;
    for (int j = threadIdx.x; j < TILE / 2; j += 256) {
        const int p = fbase + 2 * j;
        const float fx0 = flr[p * 3 + 0], fy0 = flr[p * 3 + 1];
        const float fx1 = flr[p * 3 + 3], fy1 = flr[p * 3 + 4];
        sf[j].x = pack2(-fx0, -fx1);
        sf[j].y = pack2(-fy0, -fy1);
    }
    __syncthreads();

    float m0 = __int_as_float(0x7F7FFFFF);
    float m1 = __int_as_float(0x7F7FFFFF);
    #pragma unroll 8
    for (int j = 0; j < TILE / 2; j++) {
        const ulonglong2 f = sf[j];                       // LDS.128, broadcast
        const unsigned long long dx = add2(ox2, f.x);     // ox - fx (2 lanes)
        const unsigned long long dy = add2(oy2, f.y);     // oy - fy
        const unsigned long long sq = mul2(dx, dx);       // dx*dx
        const unsigned long long d2 = fma2(dy, dy, sq);   // dy*dy + dx*dx
        float lo, hi;
        unpack2(lo, hi, d2);
        m0 = fminf(m0, lo);
        m1 = fminf(m1, hi);
    }
    g_part[blockIdx.y][objIdx] = fminf(m0, m1);
}

// ---------------------------------------------------------------------------
// Kernel B: 100-step rigid vertical drop, single block of 1024 threads,
// 8 particles per thread in registers. Exits at first contact (v_c = 0
// => asleep fires the same step).
// ---------------------------------------------------------------------------
__global__ void __launch_bounds__(1024) sim_kernel(
    const float* __restrict__ obj, float* __restrict__ out, int out_size)
{
    __shared__ unsigned s_warpmin[32];
    __shared__ unsigned s_minbits;

    const int tid = threadIdx.x;

    float z[8], mxy[8];
    bool  col[8];
    #pragma unroll
    for (int k = 0; k < 8; k++) {
        const int i = tid * 8 + k;
        z[k] = obj[i * 3 + 2];
        float m = g_part[0][i];
        #pragma unroll
        for (int c = 1; c < GY; c++) m = fminf(m, g_part[c][i]);
        mxy[k] = m;
        col[k] = false;
    }

    float tz = 0.0f, vz = 0.0f;
    float tz_first = 0.0f;        // contact translation (single contact step)
    bool  asleep = false;

    const float GDT = -9.8f * DT_F;

    for (int s = 0; s < STEPS && !asleep; s++) {
        // semi-implicit Euler (xy components stay exactly 0)
        const float vzn = vz + GDT;
        const float tzn = tz + vzn * DT_F;

        // per-particle d2 = minxy2 + dz^2 ; block-wide min via REDUX
        float d2[8];
        unsigned lbits = 0x7F7FFFFFu;
        #pragma unroll
        for (int k = 0; k < 8; k++) {
            const float dz = z[k] + tzn;
            d2[k] = fmaf(dz, dz, mxy[k]);
            lbits = min(lbits, (unsigned)__float_as_int(d2[k]));   // d2 >= 0
        }
        lbits = __reduce_min_sync(0xFFFFFFFFu, lbits);
        if ((tid & 31) == 0) s_warpmin[tid >> 5] = lbits;
        __syncthreads();
        if (tid < 32) {
            unsigned v = __reduce_min_sync(0xFFFFFFFFu, s_warpmin[tid]);
            if (tid == 0) s_minbits = v;
        }
        __syncthreads();
        const float mind2 = __int_as_float((int)s_minbits);

        // max_pen = 2R - sqrt(min d2 + eps): min commutes through monotone sqrt
        const float dmin   = sqrtf(mind2 + EPS_F);
        const float maxpen = TWO_R - dmin;
        const bool  any_c  = maxpen > 0.0f;

        const float tzc = any_c ? (tzn + maxpen) : tzn;
        const float vzc = any_c ? 0.0f : vzn;

        if (any_c) {
            // first (and only) contact step: record contacts
            #pragma unroll
            for (int k = 0; k < 8; k++) {
                const float pk = TWO_R - sqrtf(d2[k] + EPS_F);
                if (pk > 0.0f && !col[k]) col[k] = true;
            }
            tz_first = tzc;
        }

        asleep = any_c && (fabsf(vzc) < SLEEP_TH_F);  // uniform across block
        tz = tzc;
        vz = vzc;
    }

    // outputs: p_first [N,3] float32, then collision mask as 0/1 floats
    const int mask_off = out_size - N_OBJ;
    #pragma unroll
    for (int k = 0; k < 8; k++) {
        const int i = tid * 8 + k;
        out[i * 3 + 0] = obj[i * 3 + 0];
        out[i * 3 + 1] = obj[i * 3 + 1];
        out[i * 3 + 2] = col[k] ? (z[k] + tz_first) : z[k];
        if (out_size >= N_OBJ * 4)
            out[mask_off + i] = col[k] ? 1.0f : 0.0f;
    }
}

// ---------------------------------------------------------------------------
extern "C" void kernel_launch(void* const* d_in, const int* in_sizes, int n_in,
                              void* d_out, int out_size)
{
    const float* obj = (const float*)d_in[0];   // [8192,3]
    const float* flr = (const float*)d_in[1];   // [8192,3]
    float* out = (float*)d_out;

    dim3 grid(N_OBJ / 256, GY);
    minxy_kernel<<<grid, 256>>>(obj, flr);
    sim_kernel<<<1, 1024>>>(obj, out, out_size);
}

// round 10
// speedup vs baseline: 2.1667x; 2.1667x over previous
#include <cuda_runtime.h>
#include <cstdint>

#define N_OBJ   8192
#define N_FLOOR 8192
#define STEPS   100

#define DT_F        0.01f
#define TWO_R       0.002f
#define EPS_F       1e-12f

#define GY   32
#define TILE (N_FLOOR / GY)       // 256 floor points per y-block

// partial per-object min horizontal squared distance, one row per floor chunk
__device__ float    g_part[GY][N_OBJ];
__device__ float    g_mxy[N_OBJ];
__device__ unsigned g_mind2bits[STEPS];

// ---------------------------------------------------------------------------
// packed f32x2 helpers (sm_10x 2xFP32 datapath; only reachable via PTX)
// ---------------------------------------------------------------------------
__device__ __forceinline__ unsigned long long pack2(float lo, float hi) {
    unsigned long long r;
    asm("mov.b64 %0, {%1, %2};" : "=l"(r) : "f"(lo), "f"(hi));
    return r;
}
__device__ __forceinline__ void unpack2(float& lo, float& hi, unsigned long long v) {
    asm("mov.b64 {%0, %1}, %2;" : "=f"(lo), "=f"(hi) : "l"(v));
}
__device__ __forceinline__ unsigned long long add2(unsigned long long a, unsigned long long b) {
    unsigned long long r;
    asm("add.rn.f32x2 %0, %1, %2;" : "=l"(r) : "l"(a), "l"(b));
    return r;
}
__device__ __forceinline__ unsigned long long mul2(unsigned long long a, unsigned long long b) {
    unsigned long long r;
    asm("mul.rn.f32x2 %0, %1, %2;" : "=l"(r) : "l"(a), "l"(b));
    return r;
}
__device__ __forceinline__ unsigned long long fma2(unsigned long long a, unsigned long long b,
                                                   unsigned long long c) {
    unsigned long long r;
    asm("fma.rn.f32x2 %0, %1, %2, %3;" : "=l"(r) : "l"(a), "l"(b), "l"(c));
    return r;
}

// ---------------------------------------------------------------------------
// Kernel A: partial minxy2 over one 256-point floor chunk.
// grid = (N_OBJ/256, GY) = (32, 32) = 1024 blocks, 256 threads (1 object each).
// Two floor points per iteration via packed f32x2.
// ---------------------------------------------------------------------------
__global__ void __launch_bounds__(256) minxy_kernel(
    const float* __restrict__ obj, const float* __restrict__ flr)
{
    // sf[j].x = pack(-fx[2j], -fx[2j+1]), sf[j].y = pack(-fy[2j], -fy[2j+1])
    __shared__ ulonglong2 sf[TILE / 2];

    const int objIdx = blockIdx.x * 256 + threadIdx.x;
    const float ox = obj[objIdx * 3 + 0];
    const float oy = obj[objIdx * 3 + 1];
    const unsigned long long ox2 = pack2(ox, ox);
    const unsigned long long oy2 = pack2(oy, oy);

    const int fbase = blockIdx.y * TILE;
    if (threadIdx.x < TILE / 2) {
        const int p = fbase + 2 * threadIdx.x;
        sf[threadIdx.x].x = pack2(-flr[p * 3 + 0], -flr[p * 3 + 3]);
        sf[threadIdx.x].y = pack2(-flr[p * 3 + 1], -flr[p * 3 + 4]);
    }
    __syncthreads();

    float m0 = __int_as_float(0x7F7FFFFF);
    float m1 = __int_as_float(0x7F7FFFFF);
    #pragma unroll 8
    for (int j = 0; j < TILE / 2; j++) {
        const ulonglong2 f = sf[j];                       // LDS.128, broadcast
        const unsigned long long dx = add2(ox2, f.x);     // ox - fx (2 lanes)
        const unsigned long long dy = add2(oy2, f.y);     // oy - fy
        const unsigned long long sq = mul2(dx, dx);       // dx*dx
        const unsigned long long d2 = fma2(dy, dy, sq);   // dy*dy + dx*dx
        float lo, hi;
        unpack2(lo, hi, d2);
        m0 = fminf(m0, lo);
        m1 = fminf(m1, hi);
    }
    g_part[blockIdx.y][objIdx] = fminf(m0, m1);
}

// ---------------------------------------------------------------------------
// Kernel F: fold the GY partial mins -> g_mxy.  grid = 8 x 1024.
// ---------------------------------------------------------------------------
__global__ void __launch_bounds__(1024) fold_kernel()
{
    const int i = blockIdx.x * 1024 + threadIdx.x;
    float m = g_part[0][i];
    #pragma unroll
    for (int c = 1; c < GY; c++) m = fminf(m, g_part[c][i]);
    g_mxy[i] = m;
}

// ---------------------------------------------------------------------------
// Kernel B: one block per free-fall step; block s computes
//   g_mind2bits[s] = min_i bits( mxy_i + (z_i + tz_s)^2 )
// Trajectory recurrence identical (same fp expressions) to the serial version.
// ---------------------------------------------------------------------------
__global__ void __launch_bounds__(256) steps_kernel(const float* __restrict__ obj)
{
    __shared__ unsigned s_warpmin[8];

    const int s   = blockIdx.x;
    const int tid = threadIdx.x;
    const float GDT = -9.8f * DT_F;

    // free-fall tzn at step s (same ops as: vzn = vz+GDT; tzn = tz+vzn*DT)
    float vz = 0.0f, tz = 0.0f;
    for (int k = 0; k <= s; k++) {
        vz = vz + GDT;
        tz = tz + vz * DT_F;
    }

    unsigned lbits = 0x7F7FFFFFu;
    #pragma unroll 4
    for (int i = tid; i < N_OBJ; i += 256) {
        const float dz = obj[i * 3 + 2] + tz;
        const float d2 = fmaf(dz, dz, g_mxy[i]);
        lbits = min(lbits, (unsigned)__float_as_int(d2));   // d2 >= 0
    }
    lbits = __reduce_min_sync(0xFFFFFFFFu, lbits);
    if ((tid & 31) == 0) s_warpmin[tid >> 5] = lbits;
    __syncthreads();
    if (tid < 8) {
        const unsigned v = __reduce_min_sync(0xFFu, s_warpmin[tid]);
        if (tid == 0) g_mind2bits[s] = v;
    }
}

// ---------------------------------------------------------------------------
// Kernel C: find first contact step, apply contact fix, write outputs.
// grid = 8 x 1024 (one particle per thread).
// ---------------------------------------------------------------------------
__global__ void __launch_bounds__(1024) finalize_kernel(
    const float* __restrict__ obj, float* __restrict__ out, int out_size)
{
    __shared__ int   s_star;
    __shared__ float s_tzn, s_tzc;

    const int tid = threadIdx.x;
    const float GDT = -9.8f * DT_F;

    if (tid == 0) s_star = 0x7FFFFFFF;
    __syncthreads();

    float my_maxpen = 0.0f;
    if (tid < STEPS) {
        const float md     = __int_as_float((int)g_mind2bits[tid]);
        const float dmin   = sqrtf(md + EPS_F);
        my_maxpen = TWO_R - dmin;
        if (my_maxpen > 0.0f) atomicMin_block(&s_star, tid);
    }
    __syncthreads();

    const int sstar = s_star;
    if (tid == sstar) {   // the winning step's thread publishes tzn / tzc
        float vz = 0.0f, tz = 0.0f;
        for (int k = 0; k <= sstar; k++) {
            vz = vz + GDT;
            tz = tz + vz * DT_F;
        }
        s_tzn = tz;
        s_tzc = tz + my_maxpen;
    }
    __syncthreads();

    const int i = blockIdx.x * 1024 + tid;
    const float px = obj[i * 3 + 0];
    const float py = obj[i * 3 + 1];
    const float z  = obj[i * 3 + 2];

    bool  col = false;
    float pz  = z;
    if (sstar < STEPS) {
        const float dz = z + s_tzn;
        const float d2 = fmaf(dz, dz, g_mxy[i]);
        const float pk = TWO_R - sqrtf(d2 + EPS_F);
        if (pk > 0.0f) { col = true; pz = z + s_tzc; }
    }

    out[i * 3 + 0] = px;
    out[i * 3 + 1] = py;
    out[i * 3 + 2] = pz;
    if (out_size >= N_OBJ * 4)
        out[out_size - N_OBJ + i] = col ? 1.0f : 0.0f;
}

// ---------------------------------------------------------------------------
extern "C" void kernel_launch(void* const* d_in, const int* in_sizes, int n_in,
                              void* d_out, int out_size)
{
    const float* obj = (const float*)d_in[0];   // [8192,3]
    const float* flr = (const float*)d_in[1];   // [8192,3]
    float* out = (float*)d_out;

    dim3 gridA(N_OBJ / 256, GY);
    minxy_kernel<<<gridA, 256>>>(obj, flr);
    fold_kernel<<<N_OBJ / 1024, 1024>>>();
    steps_kernel<<<STEPS, 256>>>(obj);
    finalize_kernel<<<N_OBJ / 1024, 1024>>>(obj, out, out_size);
}